// round 14
// baseline (speedup 1.0000x reference)
#include <cuda_runtime.h>
#include <math.h>
#include <float.h>

#define BB 32
#define AA 8400
#define GG 40
#define CC 80
#define ROW 85
#define SP 1536      // max candidates per batch; true bound ~1080
#define SPW (SP/32)  // 48 u32 words of transposed in-region bits per (b,g)
#define MM 512       // max matched anchors per batch
#define SL 64        // in-region pairs per (b,g) cap (geometric bound ~48)

// ---------------- scratch (device globals; zero-init at load) ----------------
__device__ unsigned long long d_match[BB * AA];
__device__ unsigned long long d_inin [BB * AA];
__device__ unsigned long long d_cinin[BB * SP];
__device__ unsigned d_ginin[BB * GG * SPW];   // transposed: bit c of word -> cand
__device__ int    d_fgidx[BB * SP];
__device__ int    d_inv  [BB * AA];
__device__ int    d_fgcnt[BB];
__device__ int    d_mcnt [BB];     // zeroed by k_final each run
__device__ int    d_midx [BB * MM];
__device__ double d_acc[6];        // zeroed by k_final each run
__device__ float4 d_cbox [BB * SP];   // x1,y1,x2,y2
__device__ float4 d_cmeta[BB * SP];   // area, obj, suml, -

// ---------------- block reduction helper ----------------
__device__ __forceinline__ float blockSum(float v, float* s) {
    int tid = threadIdx.x;
#pragma unroll
    for (int o = 16; o > 0; o >>= 1) v += __shfl_xor_sync(0xffffffffu, v, o);
    if ((tid & 31) == 0) s[tid >> 5] = v;
    __syncthreads();
    float r = 0.0f;
    if (tid < (blockDim.x >> 5)) r = s[tid];
#pragma unroll
    for (int o = 4; o > 0; o >>= 1) r += __shfl_xor_sync(0xffffffffu, r, o);
    __syncthreads();
    return r;   // valid in thread 0
}

// descending compare-and-swap
#define CASD(a, b) { float _h = fmaxf(a, b), _l = fminf(a, b); a = _h; b = _l; }

// ---------------- kernel 1: analytic mask + fg-independent obj BCE ----------
__global__ void k_isin(const float* __restrict__ labels,
                       const float* __restrict__ outp) {
    __shared__ float sgx[GG], sgy[GG];
    __shared__ float s[8];
    int b = blockIdx.y;
    int tid = threadIdx.x;
    if (tid < GG) {
        sgx[tid] = labels[(b * GG + tid) * 5 + 1];
        sgy[tid] = labels[(b * GG + tid) * 5 + 2];
    }
    // zero the transposed in-region bits (61440 words) across the grid
    int gt = (blockIdx.y * gridDim.x + blockIdx.x) * blockDim.x + tid;
    if (gt < BB * GG * SPW) d_ginin[gt] = 0u;
    __syncthreads();
    int a = blockIdx.x * blockDim.x + tid;
    float vo = 0.0f;
    if (a < AA) {
        float sc; int n, rel;
        if (a < 6400)      { sc = 8.0f;  n = 80; rel = a;        }
        else if (a < 8000) { sc = 16.0f; n = 40; rel = a - 6400; }
        else               { sc = 32.0f; n = 20; rel = a - 8000; }
        float xc = ((float)(rel % n) + 0.5f) * sc;
        float yc = ((float)(rel / n) + 0.5f) * sc;
        float r  = 1.5f * sc;
        unsigned long long m = 0ull;
#pragma unroll 8
        for (int g = 0; g < GG; g++) {
            bool in = (xc > sgx[g] - r) && (xc < sgx[g] + r) &&
                      (yc > sgy[g] - r) && (yc < sgy[g] + r);
            if (in) m |= (1ull << g);
        }
        d_inin [b * AA + a] = m;
        d_match[b * AA + a] = 0ull;
        float x = outp[(size_t)(b * AA + a) * ROW + 4];
        vo = fmaxf(x, 0.0f) + __logf(1.0f + __expf(-fabsf(x)));
    }
    float r = blockSum(vo, s);
    if (tid == 0) atomicAdd(&d_acc[1], (double)r);
}

// ---------------- kernel 2: ordered compaction + transposed mask write -------
__global__ void __launch_bounds__(1024) k_scan() {
    __shared__ int wcnt[32];
    int b = blockIdx.x;
    int tid = threadIdx.x, wid = tid >> 5, lane = tid & 31;
    const int CH = 263;
    int base = wid * CH;
    int cnt = 0;
#pragma unroll
    for (int k = 0; k < 9; k++) {
        int loc = k * 32 + lane;
        int a = base + loc;
        bool p = (loc < CH) && (a < AA) && (d_inin[b * AA + a] != 0ull);
        cnt += __popc(__ballot_sync(0xffffffffu, p));
    }
    if (lane == 0) wcnt[wid] = cnt;
    __syncthreads();
    if (wid == 0) {
        int v = wcnt[lane];
#pragma unroll
        for (int o = 1; o < 32; o <<= 1) {
            int u = __shfl_up_sync(0xffffffffu, v, o);
            if (lane >= o) v += u;
        }
        wcnt[lane] = v;
    }
    __syncthreads();
    if (tid == 0) {
        int tot = wcnt[31];
        d_fgcnt[b] = tot < SP ? tot : SP;
    }
    int pos = wcnt[wid] - cnt;
#pragma unroll
    for (int k = 0; k < 9; k++) {
        int loc = k * 32 + lane;
        int a = base + loc;
        unsigned long long m =
            ((loc < CH) && (a < AA)) ? d_inin[b * AA + a] : 0ull;
        unsigned bal = __ballot_sync(0xffffffffu, m != 0ull);
        int my = __popc(bal & ((1u << lane) - 1u));
        if (m != 0ull && pos + my < SP) {
            int cp = pos + my;
            d_fgidx[b * SP + cp] = a;
            d_inv  [b * AA + a]  = cp;
            unsigned long long mm = m;
            while (mm) {
                int g = __ffsll((long long)mm) - 1;
                mm &= mm - 1;
                atomicOr(&d_ginin[(b * GG + g) * SPW + (cp >> 5)],
                         1u << (cp & 31));
            }
        }
        pos += __popc(bal);
    }
}

// ---------------- kernel 3: candidate prep + suml (16 lanes / candidate) -----
__global__ void __launch_bounds__(128) k_prep(const float* __restrict__ outp) {
    int b   = blockIdx.y;
    int cnt = d_fgcnt[b];
    if (blockIdx.x * 8 >= cnt) return;
    int tid  = threadIdx.x;
    int lane = tid & 31, warp = tid >> 5;
    int grp  = lane >> 4, sub = lane & 15;
    int i    = blockIdx.x * 8 + warp * 2 + grp;
    bool valid = (i < cnt);
    int ic = valid ? i : (cnt - 1);
    int a  = d_fgidx[b * SP + ic];
    const float* o = outp + (size_t)(b * AA + a) * ROW;
    float obj = o[4];
    float prod = 1.0f;
#pragma unroll
    for (int c = 0; c < 5; c++) {
        float x = o[5 + sub * 5 + c] * obj;
        prod *= (1.0f - x * rsqrtf(x));
    }
    float l = __logf(prod);
    l += __shfl_xor_sync(0xffffffffu, l, 1);
    l += __shfl_xor_sync(0xffffffffu, l, 2);
    l += __shfl_xor_sync(0xffffffffu, l, 4);
    l += __shfl_xor_sync(0xffffffffu, l, 8);
    if (sub == 0 && valid) {
        float bx = o[0], by = o[1], bw = o[2], bh = o[3];
        int idx = b * SP + i;
        d_cbox [idx] = make_float4(bx - bw * 0.5f, by - bh * 0.5f,
                                   bx + bw * 0.5f, by + bh * 0.5f);
        d_cmeta[idx] = make_float4(bw * bh, obj, l, 0.0f);
        d_cinin[idx] = d_inin[b * AA + a];
    }
}

// ---------------- kernel 4: fused pair iou + dynamic_k + top-k select -------
// Block per (b,g), 256 threads x <=6 candidates (dynamic trip count).
// j-loop: 1 float4 load + uniform mask word; iou in FMA pipe.
// Phase A: lane sort-6 + pop-head warp top-10 with zero early-exit.
// Phase B: k min-passes collecting winners, then parallel atomicOr.
__global__ void __launch_bounds__(256) k_pairsel(const float* __restrict__ outp,
                                                 const float* __restrict__ labels) {
    __shared__ unsigned swtop[8 * 10];
    __shared__ unsigned long long swin[10];
    __shared__ unsigned long long slist[SL];
    __shared__ int scnt;
    int bg = blockIdx.x;
    int b  = bg / GG;
    int g  = bg - b * GG;
    int tid = threadIdx.x, lane = tid & 31, wid = tid >> 5;
    int N = d_fgcnt[b];
    if (tid == 0) scnt = 0;
    if (tid < 80) swtop[tid] = 0u;

    const float* L = labels + (b * GG + g) * 5;   // uniform broadcast loads
    int   gc  = (int)L[0];
    float gxv = L[1], gyv = L[2], gwv = L[3], ghv = L[4];
    float qx1 = gxv - gwv * 0.5f, qx2 = gxv + gwv * 0.5f;
    float qy1 = gyv - ghv * 0.5f, qy2 = gyv + ghv * 0.5f;
    float qar = gwv * ghv;
    const unsigned* gin = d_ginin + (size_t)bg * SPW;
    __syncthreads();                              // scnt/swtop visible

    float s0 = 0.f, s1 = 0.f, s2 = 0.f, s3 = 0.f, s4 = 0.f, s5 = 0.f;
    float* sv[6] = {&s0, &s1, &s2, &s3, &s4, &s5};
    int jmax = (N + 255) >> 8;                    // <= 6
    for (int j = 0; j < jmax; j++) {
        int i = tid + j * 256;
        float iou = 0.0f;
        bool inreg = false;
        if (i < N) {
            float4 box = d_cbox[b * SP + i];
            float area = (box.z - box.x) * (box.w - box.y);
            float w = fminf(box.z, qx2) - fmaxf(box.x, qx1);
            float h = fminf(box.w, qy2) - fmaxf(box.y, qy1);
            float inter = fmaxf(w, 0.0f) * fmaxf(h, 0.0f);
            float den = area + qar - inter;
            float y = __uint_as_float(0x7EF311C3u - __float_as_uint(den));
            y = y * (2.0f - den * y);
            y = y * (2.0f - den * y);
            iou = inter * y;
            unsigned wrd = gin[wid + 8 * j];      // warp-uniform word
            inreg = (wrd >> lane) & 1u;
        }
        *sv[j] = iou;
        unsigned mb = __ballot_sync(0xffffffffu, inreg);
        if (mb) {
            int leader = __ffs(mb) - 1;
            int base = 0;
            if (lane == leader) base = atomicAdd(&scnt, __popc(mb));
            base = __shfl_sync(0xffffffffu, base, leader);
            if (inreg) {
                int p = base + __popc(mb & ((1u << lane) - 1u));
                if (p < SL)
                    slist[p] = ((unsigned long long)__float_as_uint(iou) << 32)
                               | (unsigned)i;
            }
        }
    }

    // phase A: sort 6 desc (12-CAS network), then pop-head top-10
    CASD(s0, s5) CASD(s1, s3) CASD(s2, s4)
    CASD(s1, s2) CASD(s3, s4)
    CASD(s0, s3) CASD(s2, s5)
    CASD(s0, s1) CASD(s2, s3) CASD(s4, s5)
    CASD(s1, s2) CASD(s3, s4)
    for (int t = 0; t < 10; t++) {
        float wmax = s0;
#pragma unroll
        for (int o = 16; o > 0; o >>= 1)
            wmax = fmaxf(wmax, __shfl_xor_sync(0xffffffffu, wmax, o));
        if (wmax <= 0.0f) break;                  // rest are zeros (pre-zeroed)
        unsigned ball = __ballot_sync(0xffffffffu, s0 == wmax);
        if (lane == (__ffs(ball) - 1)) {          // owner pops its head
            s0 = s1; s1 = s2; s2 = s3; s3 = s4; s4 = s5; s5 = 0.0f;
        }
        if (lane == 0) swtop[wid * 10 + t] = __float_as_uint(wmax);
    }
    __syncthreads();                              // appends + swtop done

    // cost burst: parallel over the <=SL in-region entries
    int M = scnt; if (M > SL) M = SL;
    if (tid < M) {
        unsigned long long e = slist[tid];
        int i = (int)(unsigned)(e & 0xFFFFFFFFull);
        float iou = __uint_as_float((unsigned)(e >> 32));
        int idx = b * SP + i;
        float4 meta = d_cmeta[idx];
        int a = d_fgidx[idx];
        float xg = outp[(size_t)(b * AA + a) * ROW + 5 + gc] * meta.y;
        float pg = xg * rsqrtf(xg);
        float cost = -meta.z - (0.5f * __logf(xg) - __logf(1.0f - pg))
                     - 3.0f * __logf(iou + 1e-8f);
        unsigned cb = __float_as_uint(cost);
        cb = (cb & 0x80000000u) ? ~cb : (cb | 0x80000000u);
        slist[tid] = ((unsigned long long)cb << 32) | (unsigned)i;
    }
    __syncthreads();

    if (wid != 0) return;
    // warp0: merge 80 per-warp tops, sum top-10 descending
    float m0 = __uint_as_float(swtop[lane]);
    float m1 = __uint_as_float(swtop[lane + 32]);
    float m2 = (lane + 64 < 80) ? __uint_as_float(swtop[lane + 64]) : 0.0f;
    CASD(m0, m1) CASD(m0, m2) CASD(m1, m2)        // sort 3 desc
    float sum = 0.0f;
    for (int t = 0; t < 10; t++) {
        float wmax = m0;
#pragma unroll
        for (int o = 16; o > 0; o >>= 1)
            wmax = fmaxf(wmax, __shfl_xor_sync(0xffffffffu, wmax, o));
        if (wmax <= 0.0f) break;
        unsigned ball = __ballot_sync(0xffffffffu, m0 == wmax);
        if (lane == (__ffs(ball) - 1)) { m0 = m1; m1 = m2; m2 = 0.0f; }
        sum += wmax;
    }
    int k = (int)sum;
    if (k < 1)  k = 1;
    if (k > 10) k = 10;

    // phase B: k smallest (cost, idx) keys; collect winners, batch atomics
    unsigned long long kk0 = (lane      < M) ? slist[lane]      : ~0ull;
    unsigned long long kk1 = (lane + 32 < M) ? slist[lane + 32] : ~0ull;
    int nwin = 0;
    for (int t = 0; t < k; t++) {
        unsigned long long lbest = (kk0 < kk1) ? kk0 : kk1;
        unsigned long long wmin = lbest;
#pragma unroll
        for (int o = 16; o > 0; o >>= 1) {
            unsigned long long oth = __shfl_xor_sync(0xffffffffu, wmin, o);
            if (oth < wmin) wmin = oth;
        }
        if (wmin == ~0ull) break;
        unsigned ball = __ballot_sync(0xffffffffu, lbest == wmin);
        if (lane == (__ffs(ball) - 1)) {          // keys unique: remove
            if (kk0 == wmin) kk0 = ~0ull; else kk1 = ~0ull;
        }
        if (lane == 0) swin[t] = wmin;
        nwin++;
    }
    __syncwarp();
    if (lane < nwin) {                            // parallel atomics (distinct a)
        int i = (int)(unsigned)(swin[lane] & 0xFFFFFFFFull);
        int a = d_fgidx[b * SP + i];
        unsigned long long old = atomicOr(&d_match[b * AA + a], 1ull << g);
        if (old == 0ull) {                        // first match -> compact
            int pos = atomicAdd(&d_mcnt[b], 1);
            if (pos < MM) d_midx[b * MM + pos] = a;
        }
    }
}

// ---------------- kernel 5: heavy losses on matched anchors only -------------
__global__ void __launch_bounds__(128) k_fgloss(const float* __restrict__ outp,
                                                const float* __restrict__ orig,
                                                const float* __restrict__ labels,
                                                const float* __restrict__ xsA,
                                                const float* __restrict__ ysA,
                                                const float* __restrict__ stA) {
    __shared__ float s[8];
    int b = blockIdx.y;
    int j = blockIdx.x * 128 + threadIdx.x;
    float v_iou = 0.0f, v_cls = 0.0f, v_l1 = 0.0f, v_obj = 0.0f;
    int mc2 = d_mcnt[b]; if (mc2 > MM) mc2 = MM;
    if (j < mc2) {
        int a = d_midx[b * MM + j];
        unsigned long long m = d_match[b * AA + a];
        int i = d_inv[b * AA + a];
        int idx = b * SP + i;
        int mg;
        if (__popcll(m) > 1) {
            // best_gt = argmin cost over in-region g's (identical formulas to
            // k_pairsel; out-of-region +1e6 costs can never win)
            float4 box  = d_cbox [idx];
            float4 meta = d_cmeta[idx];
            unsigned long long mm = d_cinin[idx];
            const float* orow = outp + (size_t)(b * AA + a) * ROW;
            float best = FLT_MAX; mg = 0;
            while (mm) {
                int g = __ffsll((long long)mm) - 1;
                mm &= mm - 1;
                const float* L = labels + (b * GG + g) * 5;
                int   gc  = (int)L[0];
                float gxv = L[1], gyv = L[2], gwv = L[3], ghv = L[4];
                float qx1 = gxv - gwv * 0.5f, qx2 = gxv + gwv * 0.5f;
                float qy1 = gyv - ghv * 0.5f, qy2 = gyv + ghv * 0.5f;
                float qar = gwv * ghv;
                float w = fminf(box.z, qx2) - fmaxf(box.x, qx1);
                float h = fminf(box.w, qy2) - fmaxf(box.y, qy1);
                float inter = fmaxf(w, 0.0f) * fmaxf(h, 0.0f);
                float den = meta.x + qar - inter;
                float y = __uint_as_float(0x7EF311C3u - __float_as_uint(den));
                y = y * (2.0f - den * y);
                y = y * (2.0f - den * y);
                float iou = inter * y;
                float xg = orow[5 + gc] * meta.y;
                float pg = xg * rsqrtf(xg);
                float c = -meta.z - (0.5f * __logf(xg) - __logf(1.0f - pg))
                          - 3.0f * __logf(iou + 1e-8f);
                if (c < best) { best = c; mg = g; }
            }
        } else {
            mg = __ffsll((long long)m) - 1;
        }
        const float* L = labels + (b * GG + mg) * 5;
        int   mc = (int)L[0];
        float gxv = L[1], gyv = L[2], gwv = L[3], ghv = L[4];

        const float* o = outp + (size_t)(b * AA + a) * ROW;
        v_obj = -o[4];                       // fg-dependent obj BCE term
        float bx = o[0], by = o[1], bw = o[2], bh = o[3];
        float tlx = fmaxf(bx - bw * 0.5f, gxv - gwv * 0.5f);
        float tly = fmaxf(by - bh * 0.5f, gyv - ghv * 0.5f);
        float brx = fminf(bx + bw * 0.5f, gxv + gwv * 0.5f);
        float bry = fminf(by + bh * 0.5f, gyv + ghv * 0.5f);
        float inter = (tlx < brx && tly < bry) ? (brx - tlx) * (bry - tly) : 0.0f;
        float pred_iou = inter / (bw * bh + gwv * ghv - inter);
        float iou      = inter / (bw * bh + gwv * ghv - inter + 1e-16f);
        v_iou = 1.0f - iou * iou;

        float cl = 0.0f;
#pragma unroll 8
        for (int c = 0; c < CC; c++) {
            float xl = o[5 + c];
            float t  = (c == mc) ? pred_iou : 0.0f;
            cl += fmaxf(xl, 0.0f) - xl * t + log1pf(expf(-fabsf(xl)));
        }
        v_cls = cl;

        float st = stA[a];
        float t0 = gxv / st - xsA[a];
        float t1 = gyv / st - ysA[a];
        float t2 = logf(gwv / st + 1e-8f);
        float t3 = logf(ghv / st + 1e-8f);
        const float* op = orig + (size_t)(b * AA + a) * 4;
        v_l1 = fabsf(op[0] - t0) + fabsf(op[1] - t1) +
               fabsf(op[2] - t2) + fabsf(op[3] - t3);
    }
    float r;
    r = blockSum(v_iou, s); if (threadIdx.x == 0) atomicAdd(&d_acc[0], (double)r);
    r = blockSum(v_obj, s); if (threadIdx.x == 0) atomicAdd(&d_acc[1], (double)r);
    r = blockSum(v_cls, s); if (threadIdx.x == 0) atomicAdd(&d_acc[2], (double)r);
    r = blockSum(v_l1,  s); if (threadIdx.x == 0) atomicAdd(&d_acc[3], (double)r);
}

// ---------------- kernel 6: finalize + reset accumulators for next replay ----
__global__ void k_final(float* out) {
    int tid = threadIdx.x;
    if (tid == 0) {
        int tot = 0;
        for (int b2 = 0; b2 < BB; b2++) tot += d_mcnt[b2];
        double nfg = (double)tot;
        if (nfg < 1.0) nfg = 1.0;
        float liou = (float)(5.0 * d_acc[0] / nfg);
        float lobj = (float)(d_acc[1] / nfg);
        float lcls = (float)(d_acc[2] / nfg);
        float ll1  = (float)(d_acc[3] / nfg);
        out[0] = liou + lobj + lcls + ll1;
        out[1] = liou;
        out[2] = lobj;
        out[3] = lcls;
        out[4] = ll1;
        out[5] = (float)(nfg / (double)(BB * GG));
    }
    __syncthreads();
    d_mcnt[tid] = 0;
    if (tid < 6) d_acc[tid] = 0.0;
}

// ---------------- launch ----------------
extern "C" void kernel_launch(void* const* d_in, const int* in_sizes, int n_in,
                              void* d_out, int out_size) {
    const float* outputs = (const float*)d_in[0];
    const float* origin  = (const float*)d_in[1];
    const float* labels  = (const float*)d_in[2];
    const float* xs      = (const float*)d_in[3];
    const float* ys      = (const float*)d_in[4];
    const float* st      = (const float*)d_in[5];

    k_isin<<<dim3((AA + 255) / 256, BB), 256>>>(labels, outputs);
    k_scan<<<BB, 1024>>>();
    k_prep<<<dim3(SP / 8, BB), 128>>>(outputs);
    k_pairsel<<<BB * GG, 256>>>(outputs, labels);
    k_fgloss<<<dim3(MM / 128, BB), 128>>>(outputs, origin, labels, xs, ys, st);
    k_final<<<1, 32>>>((float*)d_out);
}

// round 15
// speedup vs baseline: 1.0725x; 1.0725x over previous
#include <cuda_runtime.h>
#include <math.h>
#include <float.h>

#define BB 32
#define AA 8400
#define GG 40
#define CC 80
#define ROW 85
#define SP 1536      // max candidates per batch; true bound ~1080
#define SPW (SP/32)  // 48 u32 words of transposed in-region bits per (b,g)
#define MM 512       // max matched anchors per batch
#define SL 64        // in-region pairs per (b,g) cap (geometric bound ~48)

// ---------------- scratch (device globals; zero-init at load) ----------------
__device__ unsigned long long d_match[BB * AA];
__device__ unsigned long long d_inin [BB * AA];
__device__ unsigned long long d_cinin[BB * SP];
__device__ unsigned d_ginin[BB * GG * SPW];   // transposed: bit c of word -> cand
__device__ int    d_fgidx[BB * SP];
__device__ int    d_inv  [BB * AA];
__device__ int    d_fgcnt[BB];
__device__ int    d_mcnt [BB];     // zeroed by k_final each run
__device__ int    d_midx [BB * MM];
__device__ double d_acc[6];        // zeroed by k_final each run
__device__ float4 d_cbox [BB * SP];   // x1,y1,x2,y2
__device__ float4 d_cmeta[BB * SP];   // area, obj, suml, -

// ---------------- block reduction helper ----------------
__device__ __forceinline__ float blockSum(float v, float* s) {
    int tid = threadIdx.x;
#pragma unroll
    for (int o = 16; o > 0; o >>= 1) v += __shfl_xor_sync(0xffffffffu, v, o);
    if ((tid & 31) == 0) s[tid >> 5] = v;
    __syncthreads();
    float r = 0.0f;
    if (tid < (blockDim.x >> 5)) r = s[tid];
#pragma unroll
    for (int o = 4; o > 0; o >>= 1) r += __shfl_xor_sync(0xffffffffu, r, o);
    __syncthreads();
    return r;   // valid in thread 0
}

// descending compare-and-swap
#define CASD(a, b) { float _h = fmaxf(a, b), _l = fminf(a, b); a = _h; b = _l; }

// ---------------- kernel 1: analytic mask + fg-independent obj BCE ----------
__global__ void k_isin(const float* __restrict__ labels,
                       const float* __restrict__ outp) {
    __shared__ float sgx[GG], sgy[GG];
    __shared__ float s[8];
    int b = blockIdx.y;
    int tid = threadIdx.x;
    if (tid < GG) {
        sgx[tid] = labels[(b * GG + tid) * 5 + 1];
        sgy[tid] = labels[(b * GG + tid) * 5 + 2];
    }
    // zero the transposed in-region bits (61440 words) across the grid
    int gt = (blockIdx.y * gridDim.x + blockIdx.x) * blockDim.x + tid;
    if (gt < BB * GG * SPW) d_ginin[gt] = 0u;
    __syncthreads();
    int a = blockIdx.x * blockDim.x + tid;
    float vo = 0.0f;
    if (a < AA) {
        float sc; int n, rel;
        if (a < 6400)      { sc = 8.0f;  n = 80; rel = a;        }
        else if (a < 8000) { sc = 16.0f; n = 40; rel = a - 6400; }
        else               { sc = 32.0f; n = 20; rel = a - 8000; }
        float xc = ((float)(rel % n) + 0.5f) * sc;
        float yc = ((float)(rel / n) + 0.5f) * sc;
        float r  = 1.5f * sc;
        unsigned long long m = 0ull;
#pragma unroll 8
        for (int g = 0; g < GG; g++) {
            bool in = (xc > sgx[g] - r) && (xc < sgx[g] + r) &&
                      (yc > sgy[g] - r) && (yc < sgy[g] + r);
            if (in) m |= (1ull << g);
        }
        d_inin [b * AA + a] = m;
        d_match[b * AA + a] = 0ull;
        float x = outp[(size_t)(b * AA + a) * ROW + 4];
        vo = fmaxf(x, 0.0f) + __logf(1.0f + __expf(-fabsf(x)));
    }
    float r = blockSum(vo, s);
    if (tid == 0) atomicAdd(&d_acc[1], (double)r);
}

// ---------------- kernel 2: ordered compaction + transposed mask write -------
__global__ void __launch_bounds__(1024) k_scan() {
    __shared__ int wcnt[32];
    int b = blockIdx.x;
    int tid = threadIdx.x, wid = tid >> 5, lane = tid & 31;
    const int CH = 263;
    int base = wid * CH;
    int cnt = 0;
#pragma unroll
    for (int k = 0; k < 9; k++) {
        int loc = k * 32 + lane;
        int a = base + loc;
        bool p = (loc < CH) && (a < AA) && (d_inin[b * AA + a] != 0ull);
        cnt += __popc(__ballot_sync(0xffffffffu, p));
    }
    if (lane == 0) wcnt[wid] = cnt;
    __syncthreads();
    if (wid == 0) {
        int v = wcnt[lane];
#pragma unroll
        for (int o = 1; o < 32; o <<= 1) {
            int u = __shfl_up_sync(0xffffffffu, v, o);
            if (lane >= o) v += u;
        }
        wcnt[lane] = v;
    }
    __syncthreads();
    if (tid == 0) {
        int tot = wcnt[31];
        d_fgcnt[b] = tot < SP ? tot : SP;
    }
    int pos = wcnt[wid] - cnt;
#pragma unroll
    for (int k = 0; k < 9; k++) {
        int loc = k * 32 + lane;
        int a = base + loc;
        unsigned long long m =
            ((loc < CH) && (a < AA)) ? d_inin[b * AA + a] : 0ull;
        unsigned bal = __ballot_sync(0xffffffffu, m != 0ull);
        int my = __popc(bal & ((1u << lane) - 1u));
        if (m != 0ull && pos + my < SP) {
            int cp = pos + my;
            d_fgidx[b * SP + cp] = a;
            d_inv  [b * AA + a]  = cp;
            unsigned long long mm = m;
            while (mm) {
                int g = __ffsll((long long)mm) - 1;
                mm &= mm - 1;
                atomicOr(&d_ginin[(b * GG + g) * SPW + (cp >> 5)],
                         1u << (cp & 31));
            }
        }
        pos += __popc(bal);
    }
}

// ---------------- kernel 3: candidate prep + suml (16 lanes / candidate) -----
__global__ void __launch_bounds__(128) k_prep(const float* __restrict__ outp) {
    int b   = blockIdx.y;
    int cnt = d_fgcnt[b];
    if (blockIdx.x * 8 >= cnt) return;
    int tid  = threadIdx.x;
    int lane = tid & 31, warp = tid >> 5;
    int grp  = lane >> 4, sub = lane & 15;
    int i    = blockIdx.x * 8 + warp * 2 + grp;
    bool valid = (i < cnt);
    int ic = valid ? i : (cnt - 1);
    int a  = d_fgidx[b * SP + ic];
    const float* o = outp + (size_t)(b * AA + a) * ROW;
    float obj = o[4];
    float prod = 1.0f;
#pragma unroll
    for (int c = 0; c < 5; c++) {
        float x = o[5 + sub * 5 + c] * obj;
        prod *= (1.0f - x * rsqrtf(x));
    }
    float l = __logf(prod);
    l += __shfl_xor_sync(0xffffffffu, l, 1);
    l += __shfl_xor_sync(0xffffffffu, l, 2);
    l += __shfl_xor_sync(0xffffffffu, l, 4);
    l += __shfl_xor_sync(0xffffffffu, l, 8);
    if (sub == 0 && valid) {
        float bx = o[0], by = o[1], bw = o[2], bh = o[3];
        int idx = b * SP + i;
        d_cbox [idx] = make_float4(bx - bw * 0.5f, by - bh * 0.5f,
                                   bx + bw * 0.5f, by + bh * 0.5f);
        d_cmeta[idx] = make_float4(bw * bh, obj, l, 0.0f);
        d_cinin[idx] = d_inin[b * AA + a];
    }
}

// ---------------- kernel 4: fused pair iou + dynamic_k + top-k select -------
// Block per (b,g), 256 threads x 6 candidates (static unroll: registers!).
// j-loop: 1 float4 load + uniform mask word; iou in FMA pipe.
// Phase A: lane sort-6 + pop-head warp top-10 with zero early-exit.
// Phase B: k min-passes collecting winners, then parallel atomicOr.
__global__ void __launch_bounds__(256) k_pairsel(const float* __restrict__ outp,
                                                 const float* __restrict__ labels) {
    __shared__ unsigned swtop[8 * 10];
    __shared__ unsigned long long swin[10];
    __shared__ unsigned long long slist[SL];
    __shared__ int scnt;
    int bg = blockIdx.x;
    int b  = bg / GG;
    int g  = bg - b * GG;
    int tid = threadIdx.x, lane = tid & 31, wid = tid >> 5;
    int N = d_fgcnt[b];
    if (tid == 0) scnt = 0;
    if (tid < 80) swtop[tid] = 0u;

    const float* L = labels + (b * GG + g) * 5;   // uniform broadcast loads
    int   gc  = (int)L[0];
    float gxv = L[1], gyv = L[2], gwv = L[3], ghv = L[4];
    float qx1 = gxv - gwv * 0.5f, qx2 = gxv + gwv * 0.5f;
    float qy1 = gyv - ghv * 0.5f, qy2 = gyv + ghv * 0.5f;
    float qar = gwv * ghv;
    const unsigned* gin = d_ginin + (size_t)bg * SPW;
    __syncthreads();                              // scnt/swtop visible

    float s0, s1, s2, s3, s4, s5;
    float* sv[6] = {&s0, &s1, &s2, &s3, &s4, &s5};
#pragma unroll
    for (int j = 0; j < 6; j++) {
        int i = tid + j * 256;
        float iou = 0.0f;
        bool inreg = false;
        if (i < N) {
            float4 box = d_cbox[b * SP + i];
            float area = (box.z - box.x) * (box.w - box.y);
            float w = fminf(box.z, qx2) - fmaxf(box.x, qx1);
            float h = fminf(box.w, qy2) - fmaxf(box.y, qy1);
            float inter = fmaxf(w, 0.0f) * fmaxf(h, 0.0f);
            float den = area + qar - inter;
            float y = __uint_as_float(0x7EF311C3u - __float_as_uint(den));
            y = y * (2.0f - den * y);
            y = y * (2.0f - den * y);
            iou = inter * y;
            unsigned wrd = gin[wid + 8 * j];      // warp-uniform word
            inreg = (wrd >> lane) & 1u;
        }
        *sv[j] = iou;
        unsigned mb = __ballot_sync(0xffffffffu, inreg);
        if (mb) {
            int leader = __ffs(mb) - 1;
            int base = 0;
            if (lane == leader) base = atomicAdd(&scnt, __popc(mb));
            base = __shfl_sync(0xffffffffu, base, leader);
            if (inreg) {
                int p = base + __popc(mb & ((1u << lane) - 1u));
                if (p < SL)
                    slist[p] = ((unsigned long long)__float_as_uint(iou) << 32)
                               | (unsigned)i;
            }
        }
    }

    // phase A: sort 6 desc (12-CAS network), then pop-head top-10
    CASD(s0, s5) CASD(s1, s3) CASD(s2, s4)
    CASD(s1, s2) CASD(s3, s4)
    CASD(s0, s3) CASD(s2, s5)
    CASD(s0, s1) CASD(s2, s3) CASD(s4, s5)
    CASD(s1, s2) CASD(s3, s4)
    for (int t = 0; t < 10; t++) {
        float wmax = s0;
#pragma unroll
        for (int o = 16; o > 0; o >>= 1)
            wmax = fmaxf(wmax, __shfl_xor_sync(0xffffffffu, wmax, o));
        if (wmax <= 0.0f) break;                  // rest are zeros (pre-zeroed)
        unsigned ball = __ballot_sync(0xffffffffu, s0 == wmax);
        if (lane == (__ffs(ball) - 1)) {          // owner pops its head
            s0 = s1; s1 = s2; s2 = s3; s3 = s4; s4 = s5; s5 = 0.0f;
        }
        if (lane == 0) swtop[wid * 10 + t] = __float_as_uint(wmax);
    }
    __syncthreads();                              // appends + swtop done

    // cost burst: parallel over the <=SL in-region entries
    int M = scnt; if (M > SL) M = SL;
    if (tid < M) {
        unsigned long long e = slist[tid];
        int i = (int)(unsigned)(e & 0xFFFFFFFFull);
        float iou = __uint_as_float((unsigned)(e >> 32));
        int idx = b * SP + i;
        float4 meta = d_cmeta[idx];
        int a = d_fgidx[idx];
        float xg = outp[(size_t)(b * AA + a) * ROW + 5 + gc] * meta.y;
        float pg = xg * rsqrtf(xg);
        float cost = -meta.z - (0.5f * __logf(xg) - __logf(1.0f - pg))
                     - 3.0f * __logf(iou + 1e-8f);
        unsigned cb = __float_as_uint(cost);
        cb = (cb & 0x80000000u) ? ~cb : (cb | 0x80000000u);
        slist[tid] = ((unsigned long long)cb << 32) | (unsigned)i;
    }
    __syncthreads();

    if (wid != 0) return;
    // warp0: merge 80 per-warp tops, sum top-10 descending
    float m0 = __uint_as_float(swtop[lane]);
    float m1 = __uint_as_float(swtop[lane + 32]);
    float m2 = (lane + 64 < 80) ? __uint_as_float(swtop[lane + 64]) : 0.0f;
    CASD(m0, m1) CASD(m0, m2) CASD(m1, m2)        // sort 3 desc
    float sum = 0.0f;
    for (int t = 0; t < 10; t++) {
        float wmax = m0;
#pragma unroll
        for (int o = 16; o > 0; o >>= 1)
            wmax = fmaxf(wmax, __shfl_xor_sync(0xffffffffu, wmax, o));
        if (wmax <= 0.0f) break;
        unsigned ball = __ballot_sync(0xffffffffu, m0 == wmax);
        if (lane == (__ffs(ball) - 1)) { m0 = m1; m1 = m2; m2 = 0.0f; }
        sum += wmax;
    }
    int k = (int)sum;
    if (k < 1)  k = 1;
    if (k > 10) k = 10;

    // phase B: k smallest (cost, idx) keys; collect winners, batch atomics
    unsigned long long kk0 = (lane      < M) ? slist[lane]      : ~0ull;
    unsigned long long kk1 = (lane + 32 < M) ? slist[lane + 32] : ~0ull;
    int nwin = 0;
    for (int t = 0; t < k; t++) {
        unsigned long long lbest = (kk0 < kk1) ? kk0 : kk1;
        unsigned long long wmin = lbest;
#pragma unroll
        for (int o = 16; o > 0; o >>= 1) {
            unsigned long long oth = __shfl_xor_sync(0xffffffffu, wmin, o);
            if (oth < wmin) wmin = oth;
        }
        if (wmin == ~0ull) break;
        unsigned ball = __ballot_sync(0xffffffffu, lbest == wmin);
        if (lane == (__ffs(ball) - 1)) {          // keys unique: remove
            if (kk0 == wmin) kk0 = ~0ull; else kk1 = ~0ull;
        }
        if (lane == 0) swin[t] = wmin;
        nwin++;
    }
    __syncwarp();
    if (lane < nwin) {                            // parallel atomics (distinct a)
        int i = (int)(unsigned)(swin[lane] & 0xFFFFFFFFull);
        int a = d_fgidx[b * SP + i];
        unsigned long long old = atomicOr(&d_match[b * AA + a], 1ull << g);
        if (old == 0ull) {                        // first match -> compact
            int pos = atomicAdd(&d_mcnt[b], 1);
            if (pos < MM) d_midx[b * MM + pos] = a;
        }
    }
}

// ---------------- kernel 5: heavy losses on matched anchors only -------------
__global__ void __launch_bounds__(128) k_fgloss(const float* __restrict__ outp,
                                                const float* __restrict__ orig,
                                                const float* __restrict__ labels,
                                                const float* __restrict__ xsA,
                                                const float* __restrict__ ysA,
                                                const float* __restrict__ stA) {
    __shared__ float s[8];
    int b = blockIdx.y;
    int j = blockIdx.x * 128 + threadIdx.x;
    float v_iou = 0.0f, v_cls = 0.0f, v_l1 = 0.0f, v_obj = 0.0f;
    int mc2 = d_mcnt[b]; if (mc2 > MM) mc2 = MM;
    if (j < mc2) {
        int a = d_midx[b * MM + j];
        unsigned long long m = d_match[b * AA + a];
        int i = d_inv[b * AA + a];
        int idx = b * SP + i;
        int mg;
        if (__popcll(m) > 1) {
            // best_gt = argmin cost over in-region g's (identical formulas to
            // k_pairsel; out-of-region +1e6 costs can never win)
            float4 box  = d_cbox [idx];
            float4 meta = d_cmeta[idx];
            unsigned long long mm = d_cinin[idx];
            const float* orow = outp + (size_t)(b * AA + a) * ROW;
            float best = FLT_MAX; mg = 0;
            while (mm) {
                int g = __ffsll((long long)mm) - 1;
                mm &= mm - 1;
                const float* L = labels + (b * GG + g) * 5;
                int   gc  = (int)L[0];
                float gxv = L[1], gyv = L[2], gwv = L[3], ghv = L[4];
                float qx1 = gxv - gwv * 0.5f, qx2 = gxv + gwv * 0.5f;
                float qy1 = gyv - ghv * 0.5f, qy2 = gyv + ghv * 0.5f;
                float qar = gwv * ghv;
                float w = fminf(box.z, qx2) - fmaxf(box.x, qx1);
                float h = fminf(box.w, qy2) - fmaxf(box.y, qy1);
                float inter = fmaxf(w, 0.0f) * fmaxf(h, 0.0f);
                float den = meta.x + qar - inter;
                float y = __uint_as_float(0x7EF311C3u - __float_as_uint(den));
                y = y * (2.0f - den * y);
                y = y * (2.0f - den * y);
                float iou = inter * y;
                float xg = orow[5 + gc] * meta.y;
                float pg = xg * rsqrtf(xg);
                float c = -meta.z - (0.5f * __logf(xg) - __logf(1.0f - pg))
                          - 3.0f * __logf(iou + 1e-8f);
                if (c < best) { best = c; mg = g; }
            }
        } else {
            mg = __ffsll((long long)m) - 1;
        }
        const float* L = labels + (b * GG + mg) * 5;
        int   mc = (int)L[0];
        float gxv = L[1], gyv = L[2], gwv = L[3], ghv = L[4];

        const float* o = outp + (size_t)(b * AA + a) * ROW;
        v_obj = -o[4];                       // fg-dependent obj BCE term
        float bx = o[0], by = o[1], bw = o[2], bh = o[3];
        float tlx = fmaxf(bx - bw * 0.5f, gxv - gwv * 0.5f);
        float tly = fmaxf(by - bh * 0.5f, gyv - ghv * 0.5f);
        float brx = fminf(bx + bw * 0.5f, gxv + gwv * 0.5f);
        float bry = fminf(by + bh * 0.5f, gyv + ghv * 0.5f);
        float inter = (tlx < brx && tly < bry) ? (brx - tlx) * (bry - tly) : 0.0f;
        float pred_iou = inter / (bw * bh + gwv * ghv - inter);
        float iou      = inter / (bw * bh + gwv * ghv - inter + 1e-16f);
        v_iou = 1.0f - iou * iou;

        float cl = 0.0f;
#pragma unroll 8
        for (int c = 0; c < CC; c++) {
            float xl = o[5 + c];
            float t  = (c == mc) ? pred_iou : 0.0f;
            cl += fmaxf(xl, 0.0f) - xl * t + log1pf(expf(-fabsf(xl)));
        }
        v_cls = cl;

        float st = stA[a];
        float t0 = gxv / st - xsA[a];
        float t1 = gyv / st - ysA[a];
        float t2 = logf(gwv / st + 1e-8f);
        float t3 = logf(ghv / st + 1e-8f);
        const float* op = orig + (size_t)(b * AA + a) * 4;
        v_l1 = fabsf(op[0] - t0) + fabsf(op[1] - t1) +
               fabsf(op[2] - t2) + fabsf(op[3] - t3);
    }
    float r;
    r = blockSum(v_iou, s); if (threadIdx.x == 0) atomicAdd(&d_acc[0], (double)r);
    r = blockSum(v_obj, s); if (threadIdx.x == 0) atomicAdd(&d_acc[1], (double)r);
    r = blockSum(v_cls, s); if (threadIdx.x == 0) atomicAdd(&d_acc[2], (double)r);
    r = blockSum(v_l1,  s); if (threadIdx.x == 0) atomicAdd(&d_acc[3], (double)r);
}

// ---------------- kernel 6: finalize + reset accumulators for next replay ----
__global__ void k_final(float* out) {
    int tid = threadIdx.x;
    if (tid == 0) {
        int tot = 0;
        for (int b2 = 0; b2 < BB; b2++) tot += d_mcnt[b2];
        double nfg = (double)tot;
        if (nfg < 1.0) nfg = 1.0;
        float liou = (float)(5.0 * d_acc[0] / nfg);
        float lobj = (float)(d_acc[1] / nfg);
        float lcls = (float)(d_acc[2] / nfg);
        float ll1  = (float)(d_acc[3] / nfg);
        out[0] = liou + lobj + lcls + ll1;
        out[1] = liou;
        out[2] = lobj;
        out[3] = lcls;
        out[4] = ll1;
        out[5] = (float)(nfg / (double)(BB * GG));
    }
    __syncthreads();
    d_mcnt[tid] = 0;
    if (tid < 6) d_acc[tid] = 0.0;
}

// ---------------- launch ----------------
extern "C" void kernel_launch(void* const* d_in, const int* in_sizes, int n_in,
                              void* d_out, int out_size) {
    const float* outputs = (const float*)d_in[0];
    const float* origin  = (const float*)d_in[1];
    const float* labels  = (const float*)d_in[2];
    const float* xs      = (const float*)d_in[3];
    const float* ys      = (const float*)d_in[4];
    const float* st      = (const float*)d_in[5];

    k_isin<<<dim3((AA + 255) / 256, BB), 256>>>(labels, outputs);
    k_scan<<<BB, 1024>>>();
    k_prep<<<dim3(SP / 8, BB), 128>>>(outputs);
    k_pairsel<<<BB * GG, 256>>>(outputs, labels);
    k_fgloss<<<dim3(MM / 128, BB), 128>>>(outputs, origin, labels, xs, ys, st);
    k_final<<<1, 32>>>((float*)d_out);
}

// round 16
// speedup vs baseline: 1.2053x; 1.1238x over previous
#include <cuda_runtime.h>
#include <math.h>
#include <float.h>

#define BB 32
#define AA 8400
#define GG 40
#define CC 80
#define ROW 85
#define SP 1536      // max candidates per batch; true bound ~1080
#define SPW (SP/32)  // 48 u32 words of transposed in-region bits per (b,g)
#define MM 512       // max matched anchors per batch
#define SL 64        // in-region pairs per (b,g) cap (geometric bound ~48)

// ---------------- scratch (device globals; zero-init at load) ----------------
__device__ unsigned long long d_match[BB * AA];
__device__ unsigned long long d_inin [BB * AA];
__device__ unsigned long long d_cinin[BB * SP];
__device__ unsigned d_ginin[BB * GG * SPW];   // transposed: bit c of word -> cand
__device__ int    d_fgidx[BB * SP];
__device__ int    d_inv  [BB * AA];
__device__ int    d_fgcnt[BB];
__device__ int    d_mcnt [BB];     // zeroed by k_final each run
__device__ int    d_midx [BB * MM];
__device__ double d_acc[6];        // zeroed by k_final each run
__device__ float4 d_cbox [BB * SP];   // x1,y1,x2,y2
__device__ float4 d_cmeta[BB * SP];   // area, obj, suml, -

// ---------------- block reduction helper ----------------
__device__ __forceinline__ float blockSum(float v, float* s) {
    int tid = threadIdx.x;
#pragma unroll
    for (int o = 16; o > 0; o >>= 1) v += __shfl_xor_sync(0xffffffffu, v, o);
    if ((tid & 31) == 0) s[tid >> 5] = v;
    __syncthreads();
    float r = 0.0f;
    if (tid < (blockDim.x >> 5)) r = s[tid];
#pragma unroll
    for (int o = 4; o > 0; o >>= 1) r += __shfl_xor_sync(0xffffffffu, r, o);
    __syncthreads();
    return r;   // valid in thread 0
}

// descending compare-and-swap
#define CASD(a, b) { float _h = fmaxf(a, b), _l = fminf(a, b); a = _h; b = _l; }

// ---------------- kernel 1: analytic mask + fg-independent obj BCE ----------
__global__ void k_isin(const float* __restrict__ labels,
                       const float* __restrict__ outp) {
    __shared__ float sgx[GG], sgy[GG];
    __shared__ float s[8];
    int b = blockIdx.y;
    int tid = threadIdx.x;
    if (tid < GG) {
        sgx[tid] = labels[(b * GG + tid) * 5 + 1];
        sgy[tid] = labels[(b * GG + tid) * 5 + 2];
    }
    // zero the transposed in-region bits (61440 words) across the grid
    int gt = (blockIdx.y * gridDim.x + blockIdx.x) * blockDim.x + tid;
    if (gt < BB * GG * SPW) d_ginin[gt] = 0u;
    __syncthreads();
    int a = blockIdx.x * blockDim.x + tid;
    float vo = 0.0f;
    if (a < AA) {
        float sc; int n, rel;
        if (a < 6400)      { sc = 8.0f;  n = 80; rel = a;        }
        else if (a < 8000) { sc = 16.0f; n = 40; rel = a - 6400; }
        else               { sc = 32.0f; n = 20; rel = a - 8000; }
        float xc = ((float)(rel % n) + 0.5f) * sc;
        float yc = ((float)(rel / n) + 0.5f) * sc;
        float r  = 1.5f * sc;
        unsigned long long m = 0ull;
#pragma unroll 8
        for (int g = 0; g < GG; g++) {
            bool in = (xc > sgx[g] - r) && (xc < sgx[g] + r) &&
                      (yc > sgy[g] - r) && (yc < sgy[g] + r);
            if (in) m |= (1ull << g);
        }
        d_inin [b * AA + a] = m;
        d_match[b * AA + a] = 0ull;
        float x = outp[(size_t)(b * AA + a) * ROW + 4];
        vo = fmaxf(x, 0.0f) + __logf(1.0f + __expf(-fabsf(x)));
    }
    float r = blockSum(vo, s);
    if (tid == 0) atomicAdd(&d_acc[1], (double)r);
}

// ---------------- kernel 2: ordered compaction + transposed mask write -------
__global__ void __launch_bounds__(1024) k_scan() {
    __shared__ int wcnt[32];
    int b = blockIdx.x;
    int tid = threadIdx.x, wid = tid >> 5, lane = tid & 31;
    const int CH = 263;
    int base = wid * CH;
    int cnt = 0;
#pragma unroll
    for (int k = 0; k < 9; k++) {
        int loc = k * 32 + lane;
        int a = base + loc;
        bool p = (loc < CH) && (a < AA) && (d_inin[b * AA + a] != 0ull);
        cnt += __popc(__ballot_sync(0xffffffffu, p));
    }
    if (lane == 0) wcnt[wid] = cnt;
    __syncthreads();
    if (wid == 0) {
        int v = wcnt[lane];
#pragma unroll
        for (int o = 1; o < 32; o <<= 1) {
            int u = __shfl_up_sync(0xffffffffu, v, o);
            if (lane >= o) v += u;
        }
        wcnt[lane] = v;
    }
    __syncthreads();
    if (tid == 0) {
        int tot = wcnt[31];
        d_fgcnt[b] = tot < SP ? tot : SP;
    }
    int pos = wcnt[wid] - cnt;
#pragma unroll
    for (int k = 0; k < 9; k++) {
        int loc = k * 32 + lane;
        int a = base + loc;
        unsigned long long m =
            ((loc < CH) && (a < AA)) ? d_inin[b * AA + a] : 0ull;
        unsigned bal = __ballot_sync(0xffffffffu, m != 0ull);
        int my = __popc(bal & ((1u << lane) - 1u));
        if (m != 0ull && pos + my < SP) {
            int cp = pos + my;
            d_fgidx[b * SP + cp] = a;
            d_inv  [b * AA + a]  = cp;
            unsigned long long mm = m;
            while (mm) {
                int g = __ffsll((long long)mm) - 1;
                mm &= mm - 1;
                atomicOr(&d_ginin[(b * GG + g) * SPW + (cp >> 5)],
                         1u << (cp & 31));
            }
        }
        pos += __popc(bal);
    }
}

// ---------------- kernel 3: candidate prep + suml (16 lanes / candidate) -----
__global__ void __launch_bounds__(128) k_prep(const float* __restrict__ outp) {
    int b   = blockIdx.y;
    int cnt = d_fgcnt[b];
    if (blockIdx.x * 8 >= cnt) return;
    int tid  = threadIdx.x;
    int lane = tid & 31, warp = tid >> 5;
    int grp  = lane >> 4, sub = lane & 15;
    int i    = blockIdx.x * 8 + warp * 2 + grp;
    bool valid = (i < cnt);
    int ic = valid ? i : (cnt - 1);
    int a  = d_fgidx[b * SP + ic];
    const float* o = outp + (size_t)(b * AA + a) * ROW;
    float obj = o[4];
    float prod = 1.0f;
#pragma unroll
    for (int c = 0; c < 5; c++) {
        float x = o[5 + sub * 5 + c] * obj;
        prod *= (1.0f - x * rsqrtf(x));
    }
    float l = __logf(prod);
    l += __shfl_xor_sync(0xffffffffu, l, 1);
    l += __shfl_xor_sync(0xffffffffu, l, 2);
    l += __shfl_xor_sync(0xffffffffu, l, 4);
    l += __shfl_xor_sync(0xffffffffu, l, 8);
    if (sub == 0 && valid) {
        float bx = o[0], by = o[1], bw = o[2], bh = o[3];
        int idx = b * SP + i;
        d_cbox [idx] = make_float4(bx - bw * 0.5f, by - bh * 0.5f,
                                   bx + bw * 0.5f, by + bh * 0.5f);
        d_cmeta[idx] = make_float4(bw * bh, obj, l, 0.0f);
        d_cinin[idx] = d_inin[b * AA + a];
    }
}

// ---------------- kernel 4: fused pair iou + dynamic_k + top-k, 2 GTs/block --
// Block per (b, g-pair), 256 threads x 6 candidates. Candidate box loaded
// once, used for both GTs. REDUX.SYNC max replaces shfl chains. Tails for
// g0/g1 run concurrently on warps 0/1.
__global__ void __launch_bounds__(256) k_pairsel(const float* __restrict__ outp,
                                                 const float* __restrict__ labels) {
    __shared__ unsigned swtop[2][80];
    __shared__ unsigned long long swin[2][10];
    __shared__ unsigned long long slist[2][SL];
    __shared__ int scnt[2];
    int bg = blockIdx.x;
    int b  = bg / (GG / 2);
    int gp = bg - b * (GG / 2);
    int g0 = gp * 2;
    int tid = threadIdx.x, lane = tid & 31, wid = tid >> 5;
    int N = d_fgcnt[b];
    if (tid < 2) scnt[tid] = 0;
    if (tid < 160) swtop[tid >> 7][tid & 127] = 0u;   // 2 x 80 (pads ok)

    const float* L0 = labels + (b * GG + g0) * 5;     // uniform broadcasts
    const float* L1 = L0 + 5;
    int   gc0 = (int)L0[0],  gc1 = (int)L1[0];
    float ax1 = L0[1] - L0[3] * 0.5f, ax2 = L0[1] + L0[3] * 0.5f;
    float ay1 = L0[2] - L0[4] * 0.5f, ay2 = L0[2] + L0[4] * 0.5f;
    float aar = L0[3] * L0[4];
    float bx1 = L1[1] - L1[3] * 0.5f, bx2 = L1[1] + L1[3] * 0.5f;
    float by1 = L1[2] - L1[4] * 0.5f, by2 = L1[2] + L1[4] * 0.5f;
    float bar = L1[3] * L1[4];
    const unsigned* gin0 = d_ginin + (size_t)(b * GG + g0) * SPW;
    const unsigned* gin1 = gin0 + SPW;
    __syncthreads();                                  // scnt/swtop visible

    float s0, s1, s2, s3, s4, s5;                     // g0 ious
    float t0, t1, t2, t3, t4, t5;                     // g1 ious
    float* sv[6] = {&s0, &s1, &s2, &s3, &s4, &s5};
    float* tv[6] = {&t0, &t1, &t2, &t3, &t4, &t5};
#pragma unroll
    for (int j = 0; j < 6; j++) {
        int i = tid + j * 256;
        float iouA = 0.0f, iouB = 0.0f;
        bool inA = false, inB = false;
        if (i < N) {
            float4 box = d_cbox[b * SP + i];
            float area = (box.z - box.x) * (box.w - box.y);
            // g0
            float w = fminf(box.z, ax2) - fmaxf(box.x, ax1);
            float h = fminf(box.w, ay2) - fmaxf(box.y, ay1);
            float inter = fmaxf(w, 0.0f) * fmaxf(h, 0.0f);
            float den = area + aar - inter;
            float y = __uint_as_float(0x7EF311C3u - __float_as_uint(den));
            y = y * (2.0f - den * y);
            y = y * (2.0f - den * y);
            iouA = inter * y;
            // g1
            w = fminf(box.z, bx2) - fmaxf(box.x, bx1);
            h = fminf(box.w, by2) - fmaxf(box.y, by1);
            inter = fmaxf(w, 0.0f) * fmaxf(h, 0.0f);
            den = area + bar - inter;
            y = __uint_as_float(0x7EF311C3u - __float_as_uint(den));
            y = y * (2.0f - den * y);
            y = y * (2.0f - den * y);
            iouB = inter * y;
            unsigned wrd0 = gin0[wid + 8 * j];        // warp-uniform words
            unsigned wrd1 = gin1[wid + 8 * j];
            inA = (wrd0 >> lane) & 1u;
            inB = (wrd1 >> lane) & 1u;
        }
        *sv[j] = iouA;
        *tv[j] = iouB;
        unsigned mb = __ballot_sync(0xffffffffu, inA);
        if (mb) {
            int leader = __ffs(mb) - 1;
            int base = 0;
            if (lane == leader) base = atomicAdd(&scnt[0], __popc(mb));
            base = __shfl_sync(0xffffffffu, base, leader);
            if (inA) {
                int p = base + __popc(mb & ((1u << lane) - 1u));
                if (p < SL)
                    slist[0][p] = ((unsigned long long)__float_as_uint(iouA) << 32)
                                  | (unsigned)i;
            }
        }
        mb = __ballot_sync(0xffffffffu, inB);
        if (mb) {
            int leader = __ffs(mb) - 1;
            int base = 0;
            if (lane == leader) base = atomicAdd(&scnt[1], __popc(mb));
            base = __shfl_sync(0xffffffffu, base, leader);
            if (inB) {
                int p = base + __popc(mb & ((1u << lane) - 1u));
                if (p < SL)
                    slist[1][p] = ((unsigned long long)__float_as_uint(iouB) << 32)
                                  | (unsigned)i;
            }
        }
    }

    // phase A for g0: sort 6 desc, pop-head top-10 via REDUX
    CASD(s0, s5) CASD(s1, s3) CASD(s2, s4)
    CASD(s1, s2) CASD(s3, s4)
    CASD(s0, s3) CASD(s2, s5)
    CASD(s0, s1) CASD(s2, s3) CASD(s4, s5)
    CASD(s1, s2) CASD(s3, s4)
    for (int t = 0; t < 10; t++) {
        unsigned wmax = __reduce_max_sync(0xffffffffu, __float_as_uint(s0));
        if (wmax == 0u) break;
        float fm = __uint_as_float(wmax);
        unsigned ball = __ballot_sync(0xffffffffu, s0 == fm);
        if (lane == (__ffs(ball) - 1)) {
            s0 = s1; s1 = s2; s2 = s3; s3 = s4; s4 = s5; s5 = 0.0f;
        }
        if (lane == 0) swtop[0][wid * 10 + t] = wmax;
    }
    // phase A for g1
    CASD(t0, t5) CASD(t1, t3) CASD(t2, t4)
    CASD(t1, t2) CASD(t3, t4)
    CASD(t0, t3) CASD(t2, t5)
    CASD(t0, t1) CASD(t2, t3) CASD(t4, t5)
    CASD(t1, t2) CASD(t3, t4)
    for (int t = 0; t < 10; t++) {
        unsigned wmax = __reduce_max_sync(0xffffffffu, __float_as_uint(t0));
        if (wmax == 0u) break;
        float fm = __uint_as_float(wmax);
        unsigned ball = __ballot_sync(0xffffffffu, t0 == fm);
        if (lane == (__ffs(ball) - 1)) {
            t0 = t1; t1 = t2; t2 = t3; t3 = t4; t4 = t5; t5 = 0.0f;
        }
        if (lane == 0) swtop[1][wid * 10 + t] = wmax;
    }
    __syncthreads();                              // appends + swtop done

    // cost burst: halves of the block handle g0 / g1 lists in parallel
    {
        int half = tid >> 7;                      // 0 or 1
        int p = tid & 127;
        int M = scnt[half]; if (M > SL) M = SL;
        if (p < M) {
            unsigned long long e = slist[half][p];
            int i = (int)(unsigned)(e & 0xFFFFFFFFull);
            float iou = __uint_as_float((unsigned)(e >> 32));
            int idx = b * SP + i;
            float4 meta = d_cmeta[idx];
            int a = d_fgidx[idx];
            int gc = half ? gc1 : gc0;
            float xg = outp[(size_t)(b * AA + a) * ROW + 5 + gc] * meta.y;
            float pg = xg * rsqrtf(xg);
            float cost = -meta.z - (0.5f * __logf(xg) - __logf(1.0f - pg))
                         - 3.0f * __logf(iou + 1e-8f);
            unsigned cb = __float_as_uint(cost);
            cb = (cb & 0x80000000u) ? ~cb : (cb | 0x80000000u);
            slist[half][p] = ((unsigned long long)cb << 32) | (unsigned)i;
        }
    }
    __syncthreads();

    if (wid >= 2) return;
    // tails: warp 0 handles g0, warp 1 handles g1 (concurrent)
    int half = wid;
    int g = g0 + half;
    const unsigned* mytop = swtop[half];
    int M = scnt[half]; if (M > SL) M = SL;

    float m0 = __uint_as_float(mytop[lane]);
    float m1 = __uint_as_float(mytop[lane + 32]);
    float m2 = (lane + 64 < 80) ? __uint_as_float(mytop[lane + 64]) : 0.0f;
    CASD(m0, m1) CASD(m0, m2) CASD(m1, m2)        // sort 3 desc
    float sum = 0.0f;
    for (int t = 0; t < 10; t++) {
        unsigned wmax = __reduce_max_sync(0xffffffffu, __float_as_uint(m0));
        if (wmax == 0u) break;
        float fm = __uint_as_float(wmax);
        unsigned ball = __ballot_sync(0xffffffffu, m0 == fm);
        if (lane == (__ffs(ball) - 1)) { m0 = m1; m1 = m2; m2 = 0.0f; }
        sum += fm;
    }
    int k = (int)sum;
    if (k < 1)  k = 1;
    if (k > 10) k = 10;

    // phase B: k smallest (cost, idx) keys; collect winners, batch atomics
    unsigned long long kk0 = (lane      < M) ? slist[half][lane]      : ~0ull;
    unsigned long long kk1 = (lane + 32 < M) ? slist[half][lane + 32] : ~0ull;
    int nwin = 0;
    for (int t = 0; t < k; t++) {
        unsigned long long lbest = (kk0 < kk1) ? kk0 : kk1;
        unsigned long long wmin = lbest;
#pragma unroll
        for (int o = 16; o > 0; o >>= 1) {
            unsigned long long oth = __shfl_xor_sync(0xffffffffu, wmin, o);
            if (oth < wmin) wmin = oth;
        }
        if (wmin == ~0ull) break;
        unsigned ball = __ballot_sync(0xffffffffu, lbest == wmin);
        if (lane == (__ffs(ball) - 1)) {          // keys unique: remove
            if (kk0 == wmin) kk0 = ~0ull; else kk1 = ~0ull;
        }
        if (lane == 0) swin[half][t] = wmin;
        nwin++;
    }
    __syncwarp();
    if (lane < nwin) {                            // parallel atomics (distinct a)
        int i = (int)(unsigned)(swin[half][lane] & 0xFFFFFFFFull);
        int a = d_fgidx[b * SP + i];
        unsigned long long old = atomicOr(&d_match[b * AA + a], 1ull << g);
        if (old == 0ull) {                        // first match -> compact
            int pos = atomicAdd(&d_mcnt[b], 1);
            if (pos < MM) d_midx[b * MM + pos] = a;
        }
    }
}

// ---------------- kernel 5: heavy losses on matched anchors only -------------
__global__ void __launch_bounds__(128) k_fgloss(const float* __restrict__ outp,
                                                const float* __restrict__ orig,
                                                const float* __restrict__ labels,
                                                const float* __restrict__ xsA,
                                                const float* __restrict__ ysA,
                                                const float* __restrict__ stA) {
    __shared__ float s[8];
    int b = blockIdx.y;
    int j = blockIdx.x * 128 + threadIdx.x;
    float v_iou = 0.0f, v_cls = 0.0f, v_l1 = 0.0f, v_obj = 0.0f;
    int mc2 = d_mcnt[b]; if (mc2 > MM) mc2 = MM;
    if (j < mc2) {
        int a = d_midx[b * MM + j];
        unsigned long long m = d_match[b * AA + a];
        int i = d_inv[b * AA + a];
        int idx = b * SP + i;
        int mg;
        if (__popcll(m) > 1) {
            // best_gt = argmin cost over in-region g's (identical formulas to
            // k_pairsel; out-of-region +1e6 costs can never win)
            float4 box  = d_cbox [idx];
            float4 meta = d_cmeta[idx];
            unsigned long long mm = d_cinin[idx];
            const float* orow = outp + (size_t)(b * AA + a) * ROW;
            float best = FLT_MAX; mg = 0;
            while (mm) {
                int g = __ffsll((long long)mm) - 1;
                mm &= mm - 1;
                const float* L = labels + (b * GG + g) * 5;
                int   gc  = (int)L[0];
                float gxv = L[1], gyv = L[2], gwv = L[3], ghv = L[4];
                float qx1 = gxv - gwv * 0.5f, qx2 = gxv + gwv * 0.5f;
                float qy1 = gyv - ghv * 0.5f, qy2 = gyv + ghv * 0.5f;
                float qar = gwv * ghv;
                float w = fminf(box.z, qx2) - fmaxf(box.x, qx1);
                float h = fminf(box.w, qy2) - fmaxf(box.y, qy1);
                float inter = fmaxf(w, 0.0f) * fmaxf(h, 0.0f);
                float den = meta.x + qar - inter;
                float y = __uint_as_float(0x7EF311C3u - __float_as_uint(den));
                y = y * (2.0f - den * y);
                y = y * (2.0f - den * y);
                float iou = inter * y;
                float xg = orow[5 + gc] * meta.y;
                float pg = xg * rsqrtf(xg);
                float c = -meta.z - (0.5f * __logf(xg) - __logf(1.0f - pg))
                          - 3.0f * __logf(iou + 1e-8f);
                if (c < best) { best = c; mg = g; }
            }
        } else {
            mg = __ffsll((long long)m) - 1;
        }
        const float* L = labels + (b * GG + mg) * 5;
        int   mc = (int)L[0];
        float gxv = L[1], gyv = L[2], gwv = L[3], ghv = L[4];

        const float* o = outp + (size_t)(b * AA + a) * ROW;
        v_obj = -o[4];                       // fg-dependent obj BCE term
        float bx = o[0], by = o[1], bw = o[2], bh = o[3];
        float tlx = fmaxf(bx - bw * 0.5f, gxv - gwv * 0.5f);
        float tly = fmaxf(by - bh * 0.5f, gyv - ghv * 0.5f);
        float brx = fminf(bx + bw * 0.5f, gxv + gwv * 0.5f);
        float bry = fminf(by + bh * 0.5f, gyv + ghv * 0.5f);
        float inter = (tlx < brx && tly < bry) ? (brx - tlx) * (bry - tly) : 0.0f;
        float pred_iou = inter / (bw * bh + gwv * ghv - inter);
        float iou      = inter / (bw * bh + gwv * ghv - inter + 1e-16f);
        v_iou = 1.0f - iou * iou;

        float cl = 0.0f;
#pragma unroll 8
        for (int c = 0; c < CC; c++) {
            float xl = o[5 + c];
            float t  = (c == mc) ? pred_iou : 0.0f;
            cl += fmaxf(xl, 0.0f) - xl * t + log1pf(expf(-fabsf(xl)));
        }
        v_cls = cl;

        float st = stA[a];
        float t0 = gxv / st - xsA[a];
        float t1 = gyv / st - ysA[a];
        float t2 = logf(gwv / st + 1e-8f);
        float t3 = logf(ghv / st + 1e-8f);
        const float* op = orig + (size_t)(b * AA + a) * 4;
        v_l1 = fabsf(op[0] - t0) + fabsf(op[1] - t1) +
               fabsf(op[2] - t2) + fabsf(op[3] - t3);
    }
    float r;
    r = blockSum(v_iou, s); if (threadIdx.x == 0) atomicAdd(&d_acc[0], (double)r);
    r = blockSum(v_obj, s); if (threadIdx.x == 0) atomicAdd(&d_acc[1], (double)r);
    r = blockSum(v_cls, s); if (threadIdx.x == 0) atomicAdd(&d_acc[2], (double)r);
    r = blockSum(v_l1,  s); if (threadIdx.x == 0) atomicAdd(&d_acc[3], (double)r);
}

// ---------------- kernel 6: finalize + reset accumulators for next replay ----
__global__ void k_final(float* out) {
    int tid = threadIdx.x;
    if (tid == 0) {
        int tot = 0;
        for (int b2 = 0; b2 < BB; b2++) tot += d_mcnt[b2];
        double nfg = (double)tot;
        if (nfg < 1.0) nfg = 1.0;
        float liou = (float)(5.0 * d_acc[0] / nfg);
        float lobj = (float)(d_acc[1] / nfg);
        float lcls = (float)(d_acc[2] / nfg);
        float ll1  = (float)(d_acc[3] / nfg);
        out[0] = liou + lobj + lcls + ll1;
        out[1] = liou;
        out[2] = lobj;
        out[3] = lcls;
        out[4] = ll1;
        out[5] = (float)(nfg / (double)(BB * GG));
    }
    __syncthreads();
    d_mcnt[tid] = 0;
    if (tid < 6) d_acc[tid] = 0.0;
}

// ---------------- launch ----------------
extern "C" void kernel_launch(void* const* d_in, const int* in_sizes, int n_in,
                              void* d_out, int out_size) {
    const float* outputs = (const float*)d_in[0];
    const float* origin  = (const float*)d_in[1];
    const float* labels  = (const float*)d_in[2];
    const float* xs      = (const float*)d_in[3];
    const float* ys      = (const float*)d_in[4];
    const float* st      = (const float*)d_in[5];

    k_isin<<<dim3((AA + 255) / 256, BB), 256>>>(labels, outputs);
    k_scan<<<BB, 1024>>>();
    k_prep<<<dim3(SP / 8, BB), 128>>>(outputs);
    k_pairsel<<<BB * GG / 2, 256>>>(outputs, labels);
    k_fgloss<<<dim3(MM / 128, BB), 128>>>(outputs, origin, labels, xs, ys, st);
    k_final<<<1, 32>>>((float*)d_out);
}

// round 17
// speedup vs baseline: 1.3140x; 1.0902x over previous
#include <cuda_runtime.h>
#include <math.h>
#include <float.h>

#define BB 32
#define AA 8400
#define GG 40
#define CC 80
#define ROW 85
#define SP 1536      // max candidates per batch; true bound ~1080
#define SPW (SP/32)  // 48 u32 words of transposed in-region bits per (b,g)
#define MM 512       // max matched anchors per batch
#define SL 64        // in-region pairs per (b,g) cap (geometric bound ~48)

// ---------------- scratch (device globals; zero-init at load) ----------------
__device__ unsigned long long d_match[BB * AA];
__device__ unsigned long long d_inin [BB * AA];
__device__ unsigned long long d_cinin[BB * SP];
__device__ unsigned d_ginin[BB * GG * SPW];   // transposed: bit c of word -> cand
__device__ int    d_fgidx[BB * SP];
__device__ int    d_inv  [BB * AA];
__device__ int    d_fgcnt[BB];
__device__ int    d_mcnt [BB];     // zeroed by k_final each run
__device__ int    d_midx [BB * MM];
__device__ double d_acc[6];        // zeroed by k_final each run
__device__ float4 d_cbox [BB * SP];   // x1,y1,x2,y2
__device__ float4 d_cmeta[BB * SP];   // area, obj, suml, -

// ---------------- block reduction helper (blockDim <= 256) ----------------
__device__ __forceinline__ float blockSum(float v, float* s) {
    int tid = threadIdx.x;
#pragma unroll
    for (int o = 16; o > 0; o >>= 1) v += __shfl_xor_sync(0xffffffffu, v, o);
    if ((tid & 31) == 0) s[tid >> 5] = v;
    __syncthreads();
    float r = 0.0f;
    if (tid < (blockDim.x >> 5)) r = s[tid];
#pragma unroll
    for (int o = 4; o > 0; o >>= 1) r += __shfl_xor_sync(0xffffffffu, r, o);
    __syncthreads();
    return r;   // valid in thread 0
}

// descending compare-and-swap
#define CASD(a, b) { float _h = fmaxf(a, b), _l = fminf(a, b); a = _h; b = _l; }

// ---------------- kernel 1: analytic mask + fg-independent obj BCE ----------
__global__ void k_isin(const float* __restrict__ labels,
                       const float* __restrict__ outp) {
    __shared__ float sgx[GG], sgy[GG];
    __shared__ float s[8];
    int b = blockIdx.y;
    int tid = threadIdx.x;
    if (tid < GG) {
        sgx[tid] = labels[(b * GG + tid) * 5 + 1];
        sgy[tid] = labels[(b * GG + tid) * 5 + 2];
    }
    // zero the transposed in-region bits (61440 words) across the grid
    int gt = (blockIdx.y * gridDim.x + blockIdx.x) * blockDim.x + tid;
    if (gt < BB * GG * SPW) d_ginin[gt] = 0u;
    __syncthreads();
    int a = blockIdx.x * blockDim.x + tid;
    float vo = 0.0f;
    if (a < AA) {
        float x = outp[(size_t)(b * AA + a) * ROW + 4];  // hoisted: overlaps ALU
        float sc; int n, rel;
        if (a < 6400)      { sc = 8.0f;  n = 80; rel = a;        }
        else if (a < 8000) { sc = 16.0f; n = 40; rel = a - 6400; }
        else               { sc = 32.0f; n = 20; rel = a - 8000; }
        float xc = ((float)(rel % n) + 0.5f) * sc;
        float yc = ((float)(rel / n) + 0.5f) * sc;
        float r  = 1.5f * sc;
        unsigned long long m = 0ull;
#pragma unroll 8
        for (int g = 0; g < GG; g++) {
            bool in = (xc > sgx[g] - r) && (xc < sgx[g] + r) &&
                      (yc > sgy[g] - r) && (yc < sgy[g] + r);
            if (in) m |= (1ull << g);
        }
        d_inin [b * AA + a] = m;
        d_match[b * AA + a] = 0ull;
        vo = fmaxf(x, 0.0f) + __logf(1.0f + __expf(-fabsf(x)));
    }
    float r = blockSum(vo, s);
    if (tid == 0) atomicAdd(&d_acc[1], (double)r);
}

// ---------------- kernel 2: ordered compaction + transposed mask write -------
// Prefetch all 9 mask words into registers first (one latency window),
// then ballot; pass 2 reuses the registers (no second global read).
__global__ void __launch_bounds__(1024) k_scan() {
    __shared__ int wcnt[32];
    int b = blockIdx.x;
    int tid = threadIdx.x, wid = tid >> 5, lane = tid & 31;
    const int CH = 263;
    int base = wid * CH;
    unsigned long long mym[9];
#pragma unroll
    for (int k = 0; k < 9; k++) {
        int loc = k * 32 + lane;
        int a = base + loc;
        mym[k] = ((loc < CH) && (a < AA)) ? d_inin[b * AA + a] : 0ull;
    }
    int cnt = 0;
#pragma unroll
    for (int k = 0; k < 9; k++)
        cnt += __popc(__ballot_sync(0xffffffffu, mym[k] != 0ull));
    if (lane == 0) wcnt[wid] = cnt;
    __syncthreads();
    if (wid == 0) {
        int v = wcnt[lane];
#pragma unroll
        for (int o = 1; o < 32; o <<= 1) {
            int u = __shfl_up_sync(0xffffffffu, v, o);
            if (lane >= o) v += u;
        }
        wcnt[lane] = v;
    }
    __syncthreads();
    if (tid == 0) {
        int tot = wcnt[31];
        d_fgcnt[b] = tot < SP ? tot : SP;
    }
    int pos = wcnt[wid] - cnt;
#pragma unroll
    for (int k = 0; k < 9; k++) {
        unsigned long long m = mym[k];
        unsigned bal = __ballot_sync(0xffffffffu, m != 0ull);
        int my = __popc(bal & ((1u << lane) - 1u));
        if (m != 0ull && pos + my < SP) {
            int cp = pos + my;
            int a = base + k * 32 + lane;
            d_fgidx[b * SP + cp] = a;
            d_inv  [b * AA + a]  = cp;
            unsigned long long mm = m;
            while (mm) {
                int g = __ffsll((long long)mm) - 1;
                mm &= mm - 1;
                atomicOr(&d_ginin[(b * GG + g) * SPW + (cp >> 5)],
                         1u << (cp & 31));
            }
        }
        pos += __popc(bal);
    }
}

// ---------------- kernel 3: candidate prep + suml (16 lanes / candidate) -----
__global__ void __launch_bounds__(128) k_prep(const float* __restrict__ outp) {
    int b   = blockIdx.y;
    int cnt = d_fgcnt[b];
    if (blockIdx.x * 8 >= cnt) return;
    int tid  = threadIdx.x;
    int lane = tid & 31, warp = tid >> 5;
    int grp  = lane >> 4, sub = lane & 15;
    int i    = blockIdx.x * 8 + warp * 2 + grp;
    bool valid = (i < cnt);
    int ic = valid ? i : (cnt - 1);
    int a  = d_fgidx[b * SP + ic];
    const float* o = outp + (size_t)(b * AA + a) * ROW;
    float obj = o[4];
    float prod = 1.0f;
#pragma unroll
    for (int c = 0; c < 5; c++) {
        float x = o[5 + sub * 5 + c] * obj;
        prod *= (1.0f - x * rsqrtf(x));
    }
    float l = __logf(prod);
    l += __shfl_xor_sync(0xffffffffu, l, 1);
    l += __shfl_xor_sync(0xffffffffu, l, 2);
    l += __shfl_xor_sync(0xffffffffu, l, 4);
    l += __shfl_xor_sync(0xffffffffu, l, 8);
    if (sub == 0 && valid) {
        float bx = o[0], by = o[1], bw = o[2], bh = o[3];
        int idx = b * SP + i;
        d_cbox [idx] = make_float4(bx - bw * 0.5f, by - bh * 0.5f,
                                   bx + bw * 0.5f, by + bh * 0.5f);
        d_cmeta[idx] = make_float4(bw * bh, obj, l, 0.0f);
        d_cinin[idx] = d_inin[b * AA + a];
    }
}

// ---------------- kernel 4: fused pair iou + dynamic_k + top-k, 2 GTs/block --
__global__ void __launch_bounds__(256) k_pairsel(const float* __restrict__ outp,
                                                 const float* __restrict__ labels) {
    __shared__ unsigned swtop[2][80];
    __shared__ unsigned long long swin[2][10];
    __shared__ unsigned long long slist[2][SL];
    __shared__ int scnt[2];
    int bg = blockIdx.x;
    int b  = bg / (GG / 2);
    int gp = bg - b * (GG / 2);
    int g0 = gp * 2;
    int tid = threadIdx.x, lane = tid & 31, wid = tid >> 5;
    int N = d_fgcnt[b];
    if (tid < 2) scnt[tid] = 0;
    if (tid < 160) swtop[tid >> 7][tid & 127] = 0u;   // 2 x 80 (pads ok)

    const float* L0 = labels + (b * GG + g0) * 5;     // uniform broadcasts
    const float* L1 = L0 + 5;
    int   gc0 = (int)L0[0],  gc1 = (int)L1[0];
    float ax1 = L0[1] - L0[3] * 0.5f, ax2 = L0[1] + L0[3] * 0.5f;
    float ay1 = L0[2] - L0[4] * 0.5f, ay2 = L0[2] + L0[4] * 0.5f;
    float aar = L0[3] * L0[4];
    float bx1 = L1[1] - L1[3] * 0.5f, bx2 = L1[1] + L1[3] * 0.5f;
    float by1 = L1[2] - L1[4] * 0.5f, by2 = L1[2] + L1[4] * 0.5f;
    float bar = L1[3] * L1[4];
    const unsigned* gin0 = d_ginin + (size_t)(b * GG + g0) * SPW;
    const unsigned* gin1 = gin0 + SPW;
    __syncthreads();                                  // scnt/swtop visible

    float s0, s1, s2, s3, s4, s5;                     // g0 ious
    float t0, t1, t2, t3, t4, t5;                     // g1 ious
    float* sv[6] = {&s0, &s1, &s2, &s3, &s4, &s5};
    float* tv[6] = {&t0, &t1, &t2, &t3, &t4, &t5};
#pragma unroll
    for (int j = 0; j < 6; j++) {
        int i = tid + j * 256;
        float iouA = 0.0f, iouB = 0.0f;
        bool inA = false, inB = false;
        if (i < N) {
            float4 box = d_cbox[b * SP + i];
            float area = (box.z - box.x) * (box.w - box.y);
            // g0
            float w = fminf(box.z, ax2) - fmaxf(box.x, ax1);
            float h = fminf(box.w, ay2) - fmaxf(box.y, ay1);
            float inter = fmaxf(w, 0.0f) * fmaxf(h, 0.0f);
            float den = area + aar - inter;
            float y = __uint_as_float(0x7EF311C3u - __float_as_uint(den));
            y = y * (2.0f - den * y);
            y = y * (2.0f - den * y);
            iouA = inter * y;
            // g1
            w = fminf(box.z, bx2) - fmaxf(box.x, bx1);
            h = fminf(box.w, by2) - fmaxf(box.y, by1);
            inter = fmaxf(w, 0.0f) * fmaxf(h, 0.0f);
            den = area + bar - inter;
            y = __uint_as_float(0x7EF311C3u - __float_as_uint(den));
            y = y * (2.0f - den * y);
            y = y * (2.0f - den * y);
            iouB = inter * y;
            unsigned wrd0 = gin0[wid + 8 * j];        // warp-uniform words
            unsigned wrd1 = gin1[wid + 8 * j];
            inA = (wrd0 >> lane) & 1u;
            inB = (wrd1 >> lane) & 1u;
        }
        *sv[j] = iouA;
        *tv[j] = iouB;
        unsigned mb = __ballot_sync(0xffffffffu, inA);
        if (mb) {
            int leader = __ffs(mb) - 1;
            int base = 0;
            if (lane == leader) base = atomicAdd(&scnt[0], __popc(mb));
            base = __shfl_sync(0xffffffffu, base, leader);
            if (inA) {
                int p = base + __popc(mb & ((1u << lane) - 1u));
                if (p < SL)
                    slist[0][p] = ((unsigned long long)__float_as_uint(iouA) << 32)
                                  | (unsigned)i;
            }
        }
        mb = __ballot_sync(0xffffffffu, inB);
        if (mb) {
            int leader = __ffs(mb) - 1;
            int base = 0;
            if (lane == leader) base = atomicAdd(&scnt[1], __popc(mb));
            base = __shfl_sync(0xffffffffu, base, leader);
            if (inB) {
                int p = base + __popc(mb & ((1u << lane) - 1u));
                if (p < SL)
                    slist[1][p] = ((unsigned long long)__float_as_uint(iouB) << 32)
                                  | (unsigned)i;
            }
        }
    }

    // phase A for g0: sort 6 desc, pop-head top-10 via REDUX
    CASD(s0, s5) CASD(s1, s3) CASD(s2, s4)
    CASD(s1, s2) CASD(s3, s4)
    CASD(s0, s3) CASD(s2, s5)
    CASD(s0, s1) CASD(s2, s3) CASD(s4, s5)
    CASD(s1, s2) CASD(s3, s4)
    for (int t = 0; t < 10; t++) {
        unsigned wmax = __reduce_max_sync(0xffffffffu, __float_as_uint(s0));
        if (wmax == 0u) break;
        float fm = __uint_as_float(wmax);
        unsigned ball = __ballot_sync(0xffffffffu, s0 == fm);
        if (lane == (__ffs(ball) - 1)) {
            s0 = s1; s1 = s2; s2 = s3; s3 = s4; s4 = s5; s5 = 0.0f;
        }
        if (lane == 0) swtop[0][wid * 10 + t] = wmax;
    }
    // phase A for g1
    CASD(t0, t5) CASD(t1, t3) CASD(t2, t4)
    CASD(t1, t2) CASD(t3, t4)
    CASD(t0, t3) CASD(t2, t5)
    CASD(t0, t1) CASD(t2, t3) CASD(t4, t5)
    CASD(t1, t2) CASD(t3, t4)
    for (int t = 0; t < 10; t++) {
        unsigned wmax = __reduce_max_sync(0xffffffffu, __float_as_uint(t0));
        if (wmax == 0u) break;
        float fm = __uint_as_float(wmax);
        unsigned ball = __ballot_sync(0xffffffffu, t0 == fm);
        if (lane == (__ffs(ball) - 1)) {
            t0 = t1; t1 = t2; t2 = t3; t3 = t4; t4 = t5; t5 = 0.0f;
        }
        if (lane == 0) swtop[1][wid * 10 + t] = wmax;
    }
    __syncthreads();                              // appends + swtop done

    // cost burst: halves of the block handle g0 / g1 lists in parallel
    {
        int half = tid >> 7;                      // 0 or 1
        int p = tid & 127;
        int M = scnt[half]; if (M > SL) M = SL;
        if (p < M) {
            unsigned long long e = slist[half][p];
            int i = (int)(unsigned)(e & 0xFFFFFFFFull);
            float iou = __uint_as_float((unsigned)(e >> 32));
            int idx = b * SP + i;
            float4 meta = d_cmeta[idx];
            int a = d_fgidx[idx];
            int gc = half ? gc1 : gc0;
            float xg = outp[(size_t)(b * AA + a) * ROW + 5 + gc] * meta.y;
            float pg = xg * rsqrtf(xg);
            float cost = -meta.z - (0.5f * __logf(xg) - __logf(1.0f - pg))
                         - 3.0f * __logf(iou + 1e-8f);
            unsigned cb = __float_as_uint(cost);
            cb = (cb & 0x80000000u) ? ~cb : (cb | 0x80000000u);
            slist[half][p] = ((unsigned long long)cb << 32) | (unsigned)i;
        }
    }
    __syncthreads();

    if (wid >= 2) return;
    // tails: warp 0 handles g0, warp 1 handles g1 (concurrent)
    int half = wid;
    int g = g0 + half;
    const unsigned* mytop = swtop[half];
    int M = scnt[half]; if (M > SL) M = SL;

    float m0 = __uint_as_float(mytop[lane]);
    float m1 = __uint_as_float(mytop[lane + 32]);
    float m2 = (lane + 64 < 80) ? __uint_as_float(mytop[lane + 64]) : 0.0f;
    CASD(m0, m1) CASD(m0, m2) CASD(m1, m2)        // sort 3 desc
    float sum = 0.0f;
    for (int t = 0; t < 10; t++) {
        unsigned wmax = __reduce_max_sync(0xffffffffu, __float_as_uint(m0));
        if (wmax == 0u) break;
        float fm = __uint_as_float(wmax);
        unsigned ball = __ballot_sync(0xffffffffu, m0 == fm);
        if (lane == (__ffs(ball) - 1)) { m0 = m1; m1 = m2; m2 = 0.0f; }
        sum += fm;
    }
    int k = (int)sum;
    if (k < 1)  k = 1;
    if (k > 10) k = 10;

    // phase B: k smallest (cost, idx) keys; collect winners, batch atomics
    unsigned long long kk0 = (lane      < M) ? slist[half][lane]      : ~0ull;
    unsigned long long kk1 = (lane + 32 < M) ? slist[half][lane + 32] : ~0ull;
    int nwin = 0;
    for (int t = 0; t < k; t++) {
        unsigned long long lbest = (kk0 < kk1) ? kk0 : kk1;
        unsigned long long wmin = lbest;
#pragma unroll
        for (int o = 16; o > 0; o >>= 1) {
            unsigned long long oth = __shfl_xor_sync(0xffffffffu, wmin, o);
            if (oth < wmin) wmin = oth;
        }
        if (wmin == ~0ull) break;
        unsigned ball = __ballot_sync(0xffffffffu, lbest == wmin);
        if (lane == (__ffs(ball) - 1)) {          // keys unique: remove
            if (kk0 == wmin) kk0 = ~0ull; else kk1 = ~0ull;
        }
        if (lane == 0) swin[half][t] = wmin;
        nwin++;
    }
    __syncwarp();
    if (lane < nwin) {                            // parallel atomics (distinct a)
        int i = (int)(unsigned)(swin[half][lane] & 0xFFFFFFFFull);
        int a = d_fgidx[b * SP + i];
        unsigned long long old = atomicOr(&d_match[b * AA + a], 1ull << g);
        if (old == 0ull) {                        // first match -> compact
            int pos = atomicAdd(&d_mcnt[b], 1);
            if (pos < MM) d_midx[b * MM + pos] = a;
        }
    }
}

// ---------------- kernel 5: heavy losses on matched anchors only -------------
__global__ void __launch_bounds__(128) k_fgloss(const float* __restrict__ outp,
                                                const float* __restrict__ orig,
                                                const float* __restrict__ labels,
                                                const float* __restrict__ xsA,
                                                const float* __restrict__ ysA,
                                                const float* __restrict__ stA) {
    __shared__ float s[8];
    int b = blockIdx.y;
    int j = blockIdx.x * 128 + threadIdx.x;
    float v_iou = 0.0f, v_cls = 0.0f, v_l1 = 0.0f, v_obj = 0.0f;
    int mc2 = d_mcnt[b]; if (mc2 > MM) mc2 = MM;
    if (j < mc2) {
        int a = d_midx[b * MM + j];
        unsigned long long m = d_match[b * AA + a];
        int i = d_inv[b * AA + a];
        int idx = b * SP + i;
        int mg;
        if (__popcll(m) > 1) {
            // best_gt = argmin cost over in-region g's (identical formulas to
            // k_pairsel; out-of-region +1e6 costs can never win)
            float4 box  = d_cbox [idx];
            float4 meta = d_cmeta[idx];
            unsigned long long mm = d_cinin[idx];
            const float* orow = outp + (size_t)(b * AA + a) * ROW;
            float best = FLT_MAX; mg = 0;
            while (mm) {
                int g = __ffsll((long long)mm) - 1;
                mm &= mm - 1;
                const float* L = labels + (b * GG + g) * 5;
                int   gc  = (int)L[0];
                float gxv = L[1], gyv = L[2], gwv = L[3], ghv = L[4];
                float qx1 = gxv - gwv * 0.5f, qx2 = gxv + gwv * 0.5f;
                float qy1 = gyv - ghv * 0.5f, qy2 = gyv + ghv * 0.5f;
                float qar = gwv * ghv;
                float w = fminf(box.z, qx2) - fmaxf(box.x, qx1);
                float h = fminf(box.w, qy2) - fmaxf(box.y, qy1);
                float inter = fmaxf(w, 0.0f) * fmaxf(h, 0.0f);
                float den = meta.x + qar - inter;
                float y = __uint_as_float(0x7EF311C3u - __float_as_uint(den));
                y = y * (2.0f - den * y);
                y = y * (2.0f - den * y);
                float iou = inter * y;
                float xg = orow[5 + gc] * meta.y;
                float pg = xg * rsqrtf(xg);
                float c = -meta.z - (0.5f * __logf(xg) - __logf(1.0f - pg))
                          - 3.0f * __logf(iou + 1e-8f);
                if (c < best) { best = c; mg = g; }
            }
        } else {
            mg = __ffsll((long long)m) - 1;
        }
        const float* L = labels + (b * GG + mg) * 5;
        int   mc = (int)L[0];
        float gxv = L[1], gyv = L[2], gwv = L[3], ghv = L[4];

        const float* o = outp + (size_t)(b * AA + a) * ROW;
        v_obj = -o[4];                       // fg-dependent obj BCE term
        float bx = o[0], by = o[1], bw = o[2], bh = o[3];
        float tlx = fmaxf(bx - bw * 0.5f, gxv - gwv * 0.5f);
        float tly = fmaxf(by - bh * 0.5f, gyv - ghv * 0.5f);
        float brx = fminf(bx + bw * 0.5f, gxv + gwv * 0.5f);
        float bry = fminf(by + bh * 0.5f, gyv + ghv * 0.5f);
        float inter = (tlx < brx && tly < bry) ? (brx - tlx) * (bry - tly) : 0.0f;
        float pred_iou = inter / (bw * bh + gwv * ghv - inter);
        float iou      = inter / (bw * bh + gwv * ghv - inter + 1e-16f);
        v_iou = 1.0f - iou * iou;

        float cl = 0.0f;
#pragma unroll 8
        for (int c = 0; c < CC; c++) {
            float xl = o[5 + c];
            float t  = (c == mc) ? pred_iou : 0.0f;
            cl += fmaxf(xl, 0.0f) - xl * t + __logf(1.0f + __expf(-fabsf(xl)));
        }
        v_cls = cl;

        float st = stA[a];
        float t0 = gxv / st - xsA[a];
        float t1 = gyv / st - ysA[a];
        float t2 = logf(gwv / st + 1e-8f);
        float t3 = logf(ghv / st + 1e-8f);
        const float* op = orig + (size_t)(b * AA + a) * 4;
        v_l1 = fabsf(op[0] - t0) + fabsf(op[1] - t1) +
               fabsf(op[2] - t2) + fabsf(op[3] - t3);
    }
    float r;
    r = blockSum(v_iou, s); if (threadIdx.x == 0) atomicAdd(&d_acc[0], (double)r);
    r = blockSum(v_obj, s); if (threadIdx.x == 0) atomicAdd(&d_acc[1], (double)r);
    r = blockSum(v_cls, s); if (threadIdx.x == 0) atomicAdd(&d_acc[2], (double)r);
    r = blockSum(v_l1,  s); if (threadIdx.x == 0) atomicAdd(&d_acc[3], (double)r);
}

// ---------------- kernel 6: finalize + reset accumulators for next replay ----
__global__ void k_final(float* out) {
    int tid = threadIdx.x;
    if (tid == 0) {
        int tot = 0;
        for (int b2 = 0; b2 < BB; b2++) tot += d_mcnt[b2];
        double nfg = (double)tot;
        if (nfg < 1.0) nfg = 1.0;
        float liou = (float)(5.0 * d_acc[0] / nfg);
        float lobj = (float)(d_acc[1] / nfg);
        float lcls = (float)(d_acc[2] / nfg);
        float ll1  = (float)(d_acc[3] / nfg);
        out[0] = liou + lobj + lcls + ll1;
        out[1] = liou;
        out[2] = lobj;
        out[3] = lcls;
        out[4] = ll1;
        out[5] = (float)(nfg / (double)(BB * GG));
    }
    __syncthreads();
    d_mcnt[tid] = 0;
    if (tid < 6) d_acc[tid] = 0.0;
}

// ---------------- launch ----------------
extern "C" void kernel_launch(void* const* d_in, const int* in_sizes, int n_in,
                              void* d_out, int out_size) {
    const float* outputs = (const float*)d_in[0];
    const float* origin  = (const float*)d_in[1];
    const float* labels  = (const float*)d_in[2];
    const float* xs      = (const float*)d_in[3];
    const float* ys      = (const float*)d_in[4];
    const float* st      = (const float*)d_in[5];

    k_isin<<<dim3((AA + 255) / 256, BB), 256>>>(labels, outputs);
    k_scan<<<BB, 1024>>>();
    k_prep<<<dim3(SP / 8, BB), 128>>>(outputs);
    k_pairsel<<<BB * GG / 2, 256>>>(outputs, labels);
    k_fgloss<<<dim3(MM / 128, BB), 128>>>(outputs, origin, labels, xs, ys, st);
    k_final<<<1, 32>>>((float*)d_out);
}